// round 13
// baseline (speedup 1.0000x reference)
#include <cuda_runtime.h>
#include <cuda_fp16.h>
#include <cstdint>

#define BATCHN 8192
#define OUTF   512
#define KSEG   768
#define NROWS  2048
#define NSC    12            // super-chunks: K=64 each; each accumulates BOTH
                             // Uh@Wh and Ul@Wh for its K-slice (B shared)

#define BM 128
#define BN 128
#define STAGE_BYTES 49152    // Ah 16K + Al 16K + B 16K (each 128 rows x 64 halfs)
#define AL_OFF 16384
#define B_OFF  32768
#define SMEM_TOTAL (2 * STAGE_BYTES)   // 98304; 2 CTAs/SM; epilogue reuses it
#define DPITCH 132           // padded f32 row stride for epilogue (128x132x4 = 67.6KB)

// ---------------- static device scratch (allocation-rule-safe) -------------
__device__ __align__(128) __half g_Uh[BATCHN * KSEG];
__device__ __align__(128) __half g_Ul[BATCHN * KSEG];
__device__ __align__(128) __half g_Wh[NROWS * KSEG];

// ---------------- PTX helpers ----------------------------------------------
__device__ __forceinline__ uint32_t smem_u32(const void* p) {
    uint32_t a;
    asm("{ .reg .u64 t; cvta.to.shared.u64 t, %1; cvt.u32.u64 %0, t; }"
        : "=r"(a) : "l"(p));
    return a;
}
__device__ __forceinline__ void cpa16(uint32_t dst, const void* src) {
    asm volatile("cp.async.cg.shared.global [%0], [%1], 16;" :: "r"(dst), "l"(src));
}
#define CP_COMMIT() asm volatile("cp.async.commit_group;" ::: "memory")
#define CP_WAIT(n)  asm volatile("cp.async.wait_group %0;" :: "n"(n) : "memory")

#define LDSM4(r, a)                                                             \
    asm volatile("ldmatrix.sync.aligned.m8n8.x4.shared.b16 {%0,%1,%2,%3}, [%4];"\
                 : "=r"((r)[0]), "=r"((r)[1]), "=r"((r)[2]), "=r"((r)[3])       \
                 : "r"(a))

#define MMA16816(c, a, b0, b1)                                                  \
    asm volatile("mma.sync.aligned.m16n8k16.row.col.f32.f16.f16.f32 "           \
                 "{%0,%1,%2,%3}, {%4,%5,%6,%7}, {%8,%9}, {%0,%1,%2,%3};"        \
                 : "+f"((c)[0]), "+f"((c)[1]), "+f"((c)[2]), "+f"((c)[3])       \
                 : "r"((a)[0]), "r"((a)[1]), "r"((a)[2]), "r"((a)[3]),          \
                   "r"(b0), "r"(b1))

__device__ __forceinline__ float sigf(float z) { return 1.f / (1.f + __expf(-z)); }
__device__ __forceinline__ float tanhf_fast(float z) {
    return 1.f - 2.f / (__expf(2.f * z) + 1.f);
}

// ---------------- prep kernels ---------------------------------------------
// W'[row = 4*o + g][k] : k<512 -> W_h[g][o][k] ; k>=512 -> W_x[g][o][k-512]
__global__ void prep_w_kernel(
    const float* __restrict__ w0h, const float* __restrict__ w0x,
    const float* __restrict__ w1h, const float* __restrict__ w1x,
    const float* __restrict__ w2h, const float* __restrict__ w2x,
    const float* __restrict__ w3h, const float* __restrict__ w3x)
{
    int i = blockIdx.x * 256 + threadIdx.x;
    if (i >= NROWS * (KSEG / 4)) return;
    int rw = i / (KSEG / 4);
    int k4 = (i - rw * (KSEG / 4)) * 4;
    int o  = rw >> 2, g = rw & 3;
    const float* ph; const float* px;
    switch (g) {
        case 0:  ph = w0h; px = w0x; break;
        case 1:  ph = w1h; px = w1x; break;
        case 2:  ph = w2h; px = w2x; break;
        default: ph = w3h; px = w3x; break;
    }
    float4 v = (k4 < 512) ? *(const float4*)(ph + o * 512 + k4)
                          : *(const float4*)(px + o * 256 + (k4 - 512));
    float vv[4] = {v.x, v.y, v.z, v.w};
    union { __half h[4]; uint2 u; } p;
#pragma unroll
    for (int j = 0; j < 4; ++j) p.h[j] = __float2half(vv[j]);
    *(uint2*)(g_Wh + (size_t)rw * KSEG + k4) = p.u;
}

// U[b][k] : k<512 -> H[b][k] ; k>=512 -> x[b][n][k-512]; fp16 hi/lo split
__global__ void prep_u_kernel(const float* __restrict__ x,
                              const float* __restrict__ H,
                              const int* __restrict__ np)
{
    int i = blockIdx.x * 256 + threadIdx.x;
    if (i >= BATCHN * (KSEG / 4)) return;
    int b  = i / (KSEG / 4);
    int k4 = (i - b * (KSEG / 4)) * 4;
    float4 v;
    if (k4 < 512) {
        v = *(const float4*)(H + (size_t)b * 512 + k4);
    } else {
        int n = *np;
        v = *(const float4*)(x + (size_t)b * 4096 + n * 256 + (k4 - 512));
    }
    float vv[4] = {v.x, v.y, v.z, v.w};
    union { __half h[4]; uint2 u; } phh, pll;
#pragma unroll
    for (int j = 0; j < 4; ++j) {
        phh.h[j] = __float2half(vv[j]);
        pll.h[j] = __float2half(vv[j] - __half2float(phh.h[j]));
    }
    size_t p = (size_t)b * KSEG + k4;
    *(uint2*)(g_Uh + p) = phh.u;
    *(uint2*)(g_Ul + p) = pll.u;
}

// ---------------- GEMM + fused LSTM epilogue -------------------------------
// super-chunk sc covers K-slice kk = sc*64 of both terms: Uh@Wh + Ul@Wh
__device__ __forceinline__ void load_super(uint32_t sb, int stg, int sc,
                                           int bx, int by, int tid) {
    int kk = sc * 64;            // K=64 halves per super-chunk
    int r = tid >> 3;            // 0..31
    int i = tid & 7;
    uint32_t sws = ((uint32_t)(i * 16)) ^ (((uint32_t)(r & 7)) << 4);
    uint32_t base = sb + (uint32_t)(stg * STAGE_BYTES) + (uint32_t)(r * 128) + sws;
    const char* gAh = (const char*)(g_Uh + (size_t)(bx * BM + r) * KSEG + kk) + i * 16;
    const char* gAl = (const char*)(g_Ul + (size_t)(bx * BM + r) * KSEG + kk) + i * 16;
    const char* gB  = (const char*)(g_Wh + (size_t)(by * BN + r) * KSEG + kk) + i * 16;
#pragma unroll
    for (int it = 0; it < 4; ++it)       // Ah: rows r + it*32 (128 rows)
        cpa16(base + (uint32_t)(it * 32 * 128), gAh + (size_t)it * 32 * KSEG * 2);
#pragma unroll
    for (int it = 0; it < 4; ++it)       // Al
        cpa16(base + AL_OFF + (uint32_t)(it * 32 * 128), gAl + (size_t)it * 32 * KSEG * 2);
#pragma unroll
    for (int it = 0; it < 4; ++it)       // B
        cpa16(base + B_OFF + (uint32_t)(it * 32 * 128), gB + (size_t)it * 32 * KSEG * 2);
    CP_COMMIT();
}

__global__ void __launch_bounds__(256, 2)
lstm_gemm(const float* __restrict__ C,
          const float* __restrict__ fg_w_c, const float* __restrict__ fg_b,
          const float* __restrict__ ig_w_c, const float* __restrict__ ig_b,
          const float* __restrict__ in_b,
          const float* __restrict__ og_w_cn, const float* __restrict__ og_b,
          float* __restrict__ out)
{
    extern __shared__ __align__(1024) char smem[];
    uint32_t sb = smem_u32(smem);
    const int tid = threadIdx.x;
    const int l   = tid & 31;
    const int w   = tid >> 5;
    const int bx  = blockIdx.x;   // 0..63  batch tile
    const int by  = blockIdx.y;   // 0..15  N tile

    const int wm0 = (w >> 2) * 64;   // warp M origin (0,64)
    const int wn0 = (w & 3) * 32;    // warp N origin (0,32,64,96)

    // ldmatrix per-lane bases
    const int arow  = wm0 + (l & 7) + ((l >> 3) & 1) * 8;
    const int akoff = (l >> 4) * 16;
    const int brow  = wn0 + (l & 7) + ((l >> 4) & 1) * 8;
    const int bkoff = ((l >> 3) & 1) * 16;
    const uint32_t swz = (uint32_t)((l & 7) << 4);

    float acc[4][4][4];
#pragma unroll
    for (int a = 0; a < 4; ++a)
#pragma unroll
        for (int b = 0; b < 4; ++b)
#pragma unroll
            for (int d = 0; d < 4; ++d) acc[a][b][d] = 0.f;

    // prologue: stage super-chunks 0,1
    load_super(sb, 0, 0, bx, by, tid);
    load_super(sb, 1, 1, bx, by, tid);

    uint32_t af[4][4];      // A fragments, rotated in place (Ah -> Al -> Ah...)
    uint32_t bf[2][2][4];   // B fragments, double-buffered across ks

    int stg = 0;
    for (int sc = 0; sc < NSC; ++sc) {
        CP_WAIT(1);                 // super-chunk sc resident
        __syncthreads();

        uint32_t sAh = sb + (uint32_t)(stg * STAGE_BYTES);
        uint32_t sAl = sAh + AL_OFF;
        uint32_t sB  = sAh + B_OFF;

        // preload: af = Ah[ks0], bf[0] = B[ks0]
#pragma unroll
        for (int mi = 0; mi < 4; ++mi)
            LDSM4(af[mi], sAh + (uint32_t)((arow + mi * 16) * 128)
                            + ((uint32_t)akoff ^ swz));
#pragma unroll
        for (int nj = 0; nj < 2; ++nj)
            LDSM4(bf[0][nj], sB + (uint32_t)((brow + nj * 16) * 128)
                               + ((uint32_t)bkoff ^ swz));

#pragma unroll
        for (int ks = 0; ks < 4; ++ks) {
            const int cur = ks & 1, nxt = cur ^ 1;
            const uint32_t ka_l = (uint32_t)(ks * 32 + akoff) ^ swz;        // Al[ks]
            const uint32_t ka_h = (uint32_t)((ks + 1) * 32 + akoff) ^ swz;  // Ah[ks+1]
            const uint32_t kb   = (uint32_t)((ks + 1) * 32 + bkoff) ^ swz;  // B[ks+1]

            // phase H: acc += Ah[ks] * B[ks]; rotate af -> Al[ks]
#pragma unroll
            for (int mi = 0; mi < 4; ++mi) {
                MMA16816(acc[mi][0], af[mi], bf[cur][0][0], bf[cur][0][1]);
                MMA16816(acc[mi][1], af[mi], bf[cur][0][2], bf[cur][0][3]);
                MMA16816(acc[mi][2], af[mi], bf[cur][1][0], bf[cur][1][1]);
                MMA16816(acc[mi][3], af[mi], bf[cur][1][2], bf[cur][1][3]);
                LDSM4(af[mi], sAl + (uint32_t)((arow + mi * 16) * 128) + ka_l);
            }
            if (ks < 3) {           // prefetch B[ks+1]
#pragma unroll
                for (int nj = 0; nj < 2; ++nj)
                    LDSM4(bf[nxt][nj], sB + (uint32_t)((brow + nj * 16) * 128) + kb);
            }
            // phase L: acc += Al[ks] * B[ks]; rotate af -> Ah[ks+1]
#pragma unroll
            for (int mi = 0; mi < 4; ++mi) {
                MMA16816(acc[mi][0], af[mi], bf[cur][0][0], bf[cur][0][1]);
                MMA16816(acc[mi][1], af[mi], bf[cur][0][2], bf[cur][0][3]);
                MMA16816(acc[mi][2], af[mi], bf[cur][1][0], bf[cur][1][1]);
                MMA16816(acc[mi][3], af[mi], bf[cur][1][2], bf[cur][1][3]);
                if (ks < 3)
                    LDSM4(af[mi], sAh + (uint32_t)((arow + mi * 16) * 128) + ka_h);
            }
        }

        __syncthreads();            // all reads of stage done; safe to overwrite
        if (sc + 2 < NSC) load_super(sb, stg, sc + 2, bx, by, tid);
        else              CP_COMMIT();   // empty group keeps wait accounting exact
        stg ^= 1;
    }

    // ---------------- epilogue ---------------------------------------------
    __syncthreads();   // reuse smem for D tile
    float* Ds = (float*)smem;
#pragma unroll
    for (int mi = 0; mi < 4; ++mi) {
#pragma unroll
        for (int cj = 0; cj < 4; ++cj) {
            int r0 = wm0 + mi * 16 + (l >> 2);
            int cb = wn0 + cj * 8 + (l & 3) * 2;
            Ds[r0 * DPITCH + cb]           = acc[mi][cj][0];
            Ds[r0 * DPITCH + cb + 1]       = acc[mi][cj][1];
            Ds[(r0 + 8) * DPITCH + cb]     = acc[mi][cj][2];
            Ds[(r0 + 8) * DPITCH + cb + 1] = acc[mi][cj][3];
        }
    }
    __syncthreads();

    const int ol = tid & 31;          // local output feature 0..31
    const int m0 = tid >> 5;          // 0..7 (16 rows each)
    const int og = by * 32 + ol;      // global output feature
    const float wcf = fg_w_c[og], wci = ig_w_c[og], wco = og_w_cn[og];
    const float bff = fg_b[og], bii = ig_b[og], bnn = in_b[og], boo = og_b[og];

#pragma unroll 4
    for (int r = 0; r < 16; ++r) {
        int m = m0 * 16 + r;
        int b = bx * BM + m;
        float4 z = *(const float4*)&Ds[m * DPITCH + ol * 4];
        float Cv = C[(size_t)b * OUTF + og];
        float zf = z.x + wcf * Cv + bff;
        float zi = z.y + wci * Cv + bii;
        float zn = z.z + bnn;
        float cm = sigf(zf) * Cv + sigf(zi) * tanhf_fast(zn);
        float zo = z.w + wco * cm + boo;
        float h  = sigf(zo) * tanhf_fast(cm);
        out[(size_t)b * OUTF + og] = cm;
        out[(size_t)BATCHN * OUTF + (size_t)b * OUTF + og] = h;
    }
}

// ---------------- launch ----------------------------------------------------
extern "C" void kernel_launch(void* const* d_in, const int* in_sizes, int n_in,
                              void* d_out, int out_size) {
    const float* x      = (const float*)d_in[0];
    const float* C      = (const float*)d_in[1];
    const float* H      = (const float*)d_in[2];
    const float* fg_w_c = (const float*)d_in[3];
    const float* fg_w_h = (const float*)d_in[4];
    const float* fg_w_x = (const float*)d_in[5];
    const float* fg_b   = (const float*)d_in[6];
    const float* ig_w_c = (const float*)d_in[7];
    const float* ig_w_h = (const float*)d_in[8];
    const float* ig_w_x = (const float*)d_in[9];
    const float* ig_b   = (const float*)d_in[10];
    const float* in_w_h = (const float*)d_in[11];
    const float* in_w_x = (const float*)d_in[12];
    const float* in_b   = (const float*)d_in[13];
    const float* og_w_cn= (const float*)d_in[14];
    const float* og_w_h = (const float*)d_in[15];
    const float* og_w_x = (const float*)d_in[16];
    const float* og_b   = (const float*)d_in[17];
    const int*   n      = (const int*)d_in[18];
    float* out = (float*)d_out;

    prep_w_kernel<<<(NROWS * (KSEG / 4) + 255) / 256, 256>>>(
        fg_w_h, fg_w_x, ig_w_h, ig_w_x, in_w_h, in_w_x, og_w_h, og_w_x);
    prep_u_kernel<<<(BATCHN * (KSEG / 4) + 255) / 256, 256>>>(x, H, n);

    static bool attr_done = false;
    if (!attr_done) {
        cudaFuncSetAttribute(lstm_gemm,
                             cudaFuncAttributeMaxDynamicSharedMemorySize, SMEM_TOTAL);
        attr_done = true;
    }
    dim3 grid(BATCHN / BM, NROWS / BN);
    lstm_gemm<<<grid, 256, SMEM_TOTAL>>>(
        C, fg_w_c, fg_b, ig_w_c, ig_b, in_b, og_w_cn, og_b, out);
}

// round 16
// speedup vs baseline: 1.1612x; 1.1612x over previous
#include <cuda_runtime.h>
#include <cuda_fp16.h>
#include <cstdint>

#define BATCHN 8192
#define OUTF   512
#define KSEG   768
#define NROWS  2048
#define NCHUNK 24            // 2 segments x 12 chunks of K=64

#define BM 128
#define BN 128
#define BK 64
#define STAGES 3
#define STAGE_BYTES 32768    // A 16KB + B 16KB
#define A_BYTES 16384
#define SMEM_TOTAL (STAGES * STAGE_BYTES)   // 98304; 2 CTAs/SM; epilogue reuses it
#define DPITCH 132           // padded f32 row stride for epilogue (128x132x4 = 67.6KB)

// ---------------- static device scratch (allocation-rule-safe) -------------
__device__ __align__(128) __half g_Uh[BATCHN * KSEG];
__device__ __align__(128) __half g_Ul[BATCHN * KSEG];
__device__ __align__(128) __half g_Wh[NROWS * KSEG];

// ---------------- PTX helpers ----------------------------------------------
__device__ __forceinline__ uint32_t smem_u32(const void* p) {
    uint32_t a;
    asm("{ .reg .u64 t; cvta.to.shared.u64 t, %1; cvt.u32.u64 %0, t; }"
        : "=r"(a) : "l"(p));
    return a;
}
__device__ __forceinline__ void cpa16(uint32_t dst, const void* src) {
    asm volatile("cp.async.cg.shared.global [%0], [%1], 16;" :: "r"(dst), "l"(src));
}
#define CP_COMMIT() asm volatile("cp.async.commit_group;" ::: "memory")
#define CP_WAIT(n)  asm volatile("cp.async.wait_group %0;" :: "n"(n) : "memory")

#define LDSM4(r, a)                                                             \
    asm volatile("ldmatrix.sync.aligned.m8n8.x4.shared.b16 {%0,%1,%2,%3}, [%4];"\
                 : "=r"((r)[0]), "=r"((r)[1]), "=r"((r)[2]), "=r"((r)[3])       \
                 : "r"(a))

#define MMA16816(c, a, b0, b1)                                                  \
    asm volatile("mma.sync.aligned.m16n8k16.row.col.f32.f16.f16.f32 "           \
                 "{%0,%1,%2,%3}, {%4,%5,%6,%7}, {%8,%9}, {%0,%1,%2,%3};"        \
                 : "+f"((c)[0]), "+f"((c)[1]), "+f"((c)[2]), "+f"((c)[3])       \
                 : "r"((a)[0]), "r"((a)[1]), "r"((a)[2]), "r"((a)[3]),          \
                   "r"(b0), "r"(b1))

__device__ __forceinline__ float sigf(float z) { return 1.f / (1.f + __expf(-z)); }
__device__ __forceinline__ float tanhf_fast(float z) {
    return 1.f - 2.f / (__expf(2.f * z) + 1.f);
}

// ---------------- prep kernels ---------------------------------------------
// W'[row = 4*o + g][k] : k<512 -> W_h[g][o][k] ; k>=512 -> W_x[g][o][k-512]
__global__ void prep_w_kernel(
    const float* __restrict__ w0h, const float* __restrict__ w0x,
    const float* __restrict__ w1h, const float* __restrict__ w1x,
    const float* __restrict__ w2h, const float* __restrict__ w2x,
    const float* __restrict__ w3h, const float* __restrict__ w3x)
{
    int i = blockIdx.x * 256 + threadIdx.x;
    if (i >= NROWS * (KSEG / 4)) return;
    int rw = i / (KSEG / 4);
    int k4 = (i - rw * (KSEG / 4)) * 4;
    int o  = rw >> 2, g = rw & 3;
    const float* ph; const float* px;
    switch (g) {
        case 0:  ph = w0h; px = w0x; break;
        case 1:  ph = w1h; px = w1x; break;
        case 2:  ph = w2h; px = w2x; break;
        default: ph = w3h; px = w3x; break;
    }
    float4 v = (k4 < 512) ? *(const float4*)(ph + o * 512 + k4)
                          : *(const float4*)(px + o * 256 + (k4 - 512));
    float vv[4] = {v.x, v.y, v.z, v.w};
    union { __half h[4]; uint2 u; } p;
#pragma unroll
    for (int j = 0; j < 4; ++j) p.h[j] = __float2half(vv[j]);
    *(uint2*)(g_Wh + (size_t)rw * KSEG + k4) = p.u;
}

// U[b][k] : k<512 -> H[b][k] ; k>=512 -> x[b][n][k-512]; fp16 hi/lo split
__global__ void prep_u_kernel(const float* __restrict__ x,
                              const float* __restrict__ H,
                              const int* __restrict__ np)
{
    int i = blockIdx.x * 256 + threadIdx.x;
    if (i >= BATCHN * (KSEG / 4)) return;
    int b  = i / (KSEG / 4);
    int k4 = (i - b * (KSEG / 4)) * 4;
    float4 v;
    if (k4 < 512) {
        v = *(const float4*)(H + (size_t)b * 512 + k4);
    } else {
        int n = *np;
        v = *(const float4*)(x + (size_t)b * 4096 + n * 256 + (k4 - 512));
    }
    float vv[4] = {v.x, v.y, v.z, v.w};
    union { __half h[4]; uint2 u; } phh, pll;
#pragma unroll
    for (int j = 0; j < 4; ++j) {
        phh.h[j] = __float2half(vv[j]);
        pll.h[j] = __float2half(vv[j] - __half2float(phh.h[j]));
    }
    size_t p = (size_t)b * KSEG + k4;
    *(uint2*)(g_Uh + p) = phh.u;
    *(uint2*)(g_Ul + p) = pll.u;
}

// ---------------- GEMM + fused LSTM epilogue -------------------------------
// chunk c: seg = c/12 (0: Uh*Wh, 1: Ul*Wh), kk = (c%12)*64
__device__ __forceinline__ void load_chunk(uint32_t sb, int stg, int c,
                                           int bx, int by, int tid) {
    int seg = c / 12;
    int kk  = (c - seg * 12) * BK;
    const __half* As = (seg == 1) ? g_Ul : g_Uh;
    int r = tid >> 3;            // 0..31
    int i = tid & 7;
    uint32_t sws = ((uint32_t)(i * 16)) ^ (((uint32_t)(r & 7)) << 4);
    uint32_t aA = sb + (uint32_t)(stg * STAGE_BYTES) + (uint32_t)(r * 128) + sws;
    uint32_t aB = aA + A_BYTES;
    const char* gA = (const char*)(As   + (size_t)(bx * BM + r) * KSEG + kk) + i * 16;
    const char* gB = (const char*)(g_Wh + (size_t)(by * BN + r) * KSEG + kk) + i * 16;
#pragma unroll
    for (int it = 0; it < 4; ++it)       // A: rows r + it*32 (128 rows)
        cpa16(aA + (uint32_t)(it * 32 * 128), gA + (size_t)it * 32 * KSEG * 2);
#pragma unroll
    for (int it = 0; it < 4; ++it)       // B: rows r + it*32 (128 rows)
        cpa16(aB + (uint32_t)(it * 32 * 128), gB + (size_t)it * 32 * KSEG * 2);
    CP_COMMIT();
}

__global__ void __launch_bounds__(256, 2)
lstm_gemm(const float* __restrict__ C,
          const float* __restrict__ fg_w_c, const float* __restrict__ fg_b,
          const float* __restrict__ ig_w_c, const float* __restrict__ ig_b,
          const float* __restrict__ in_b,
          const float* __restrict__ og_w_cn, const float* __restrict__ og_b,
          float* __restrict__ out)
{
    extern __shared__ __align__(1024) char smem[];
    uint32_t sb = smem_u32(smem);
    const int tid = threadIdx.x;
    const int l   = tid & 31;
    const int w   = tid >> 5;
    const int bx  = blockIdx.x;   // 0..63  batch tile
    const int by  = blockIdx.y;   // 0..15  N tile

    const int wm0 = (w >> 2) * 64;   // warp M origin (0,64)
    const int wn0 = (w & 3) * 32;    // warp N origin (0,32,64,96)

    // ldmatrix per-lane bases
    const int arow  = wm0 + (l & 7) + ((l >> 3) & 1) * 8;
    const int akoff = (l >> 4) * 16;
    const int brow  = wn0 + (l & 7) + ((l >> 4) & 1) * 8;
    const int bkoff = ((l >> 3) & 1) * 16;
    const uint32_t swz = (uint32_t)((l & 7) << 4);

    // per-thread cp.async lanes
    const int lr = tid >> 3;         // 0..31
    const int li = tid & 7;
    const uint32_t lsw = ((uint32_t)(li * 16)) ^ (((uint32_t)(lr & 7)) << 4);

    float acc[4][4][4];
#pragma unroll
    for (int a = 0; a < 4; ++a)
#pragma unroll
        for (int b = 0; b < 4; ++b)
#pragma unroll
            for (int d = 0; d < 4; ++d) acc[a][b][d] = 0.f;

    // prologue: stage chunks 0,1
    load_chunk(sb, 0, 0, bx, by, tid);
    load_chunk(sb, 1, 1, bx, by, tid);

    uint32_t af[4][4];      // A fragments, rotated in place across ks
    uint32_t bf[2][2][4];   // B fragments, double-buffered across ks

    // chunk 0 certified (2 commits outstanding -> wait to <=1)
    CP_WAIT(1);
    __syncthreads();
    // preload chunk 0 ks=0 fragments
#pragma unroll
    for (int mi = 0; mi < 4; ++mi)
        LDSM4(af[mi], sb + (uint32_t)((arow + mi * 16) * 128) + ((uint32_t)akoff ^ swz));
#pragma unroll
    for (int nj = 0; nj < 2; ++nj)
        LDSM4(bf[0][nj], sb + A_BYTES + (uint32_t)((brow + nj * 16) * 128)
                            + ((uint32_t)bkoff ^ swz));

    int stg = 0;            // stage holding chunk c
    int ldst = 2;           // stage receiving chunk c+2
    for (int c = 0; c < NCHUNK; ++c) {
        // set up interleaved loads for chunk c+2 into stage ldst
        const int  cc  = c + 2;
        const bool dol = cc < NCHUNK;
        const int  sg  = (cc >= 12) ? 1 : 0;
        const int  kk2 = (cc - sg * 12) * BK;
        const __half* As = sg ? g_Ul : g_Uh;
        const char* gA = (const char*)(As   + (size_t)(bx * BM + lr) * KSEG + kk2) + li * 16;
        const char* gB = (const char*)(g_Wh + (size_t)(by * BN + lr) * KSEG + kk2) + li * 16;
        uint32_t dA = sb + (uint32_t)(ldst * STAGE_BYTES) + (uint32_t)(lr * 128) + lsw;
        uint32_t dB = dA + A_BYTES;

        uint32_t sA = sb + (uint32_t)(stg * STAGE_BYTES);
        uint32_t sB = sA + A_BYTES;

#pragma unroll
        for (int ks = 0; ks < 4; ++ks) {
            const int cur = ks & 1, nxt = cur ^ 1;
            const uint32_t ka = (uint32_t)((ks + 1) * 32 + akoff) ^ swz;
            const uint32_t kb = (uint32_t)((ks + 1) * 32 + bkoff) ^ swz;

            // interleave 2 of the 8 cp.asyncs for chunk c+2
            if (dol) {
                cpa16(dA + (uint32_t)(ks * 32 * 128), gA + (size_t)ks * 32 * KSEG * 2);
                cpa16(dB + (uint32_t)(ks * 32 * 128), gB + (size_t)ks * 32 * KSEG * 2);
            }
            if (ks < 3) {           // prefetch B fragments for ks+1
#pragma unroll
                for (int nj = 0; nj < 2; ++nj)
                    LDSM4(bf[nxt][nj], sB + (uint32_t)((brow + nj * 16) * 128) + kb);
            }
#pragma unroll
            for (int mi = 0; mi < 4; ++mi) {
                MMA16816(acc[mi][0], af[mi], bf[cur][0][0], bf[cur][0][1]);
                MMA16816(acc[mi][1], af[mi], bf[cur][0][2], bf[cur][0][3]);
                MMA16816(acc[mi][2], af[mi], bf[cur][1][0], bf[cur][1][1]);
                MMA16816(acc[mi][3], af[mi], bf[cur][1][2], bf[cur][1][3]);
                if (ks < 3)         // af[mi] consumed; reload for ks+1 in place
                    LDSM4(af[mi], sA + (uint32_t)((arow + mi * 16) * 128) + ka);
            }
        }

        CP_COMMIT();                // close group for chunk c+2 (empty if !dol)
        CP_WAIT(1);                 // certifies chunk c+1 (only c+2 may be pending)
        __syncthreads();            // c+1 visible to all; stage stg reads all done

        if (c + 1 < NCHUNK) {       // preload chunk c+1 ks=0 fragments
            uint32_t nA = sb + (uint32_t)(((c + 1) % STAGES) * STAGE_BYTES);
#pragma unroll
            for (int mi = 0; mi < 4; ++mi)
                LDSM4(af[mi], nA + (uint32_t)((arow + mi * 16) * 128)
                                + ((uint32_t)akoff ^ swz));
#pragma unroll
            for (int nj = 0; nj < 2; ++nj)
                LDSM4(bf[0][nj], nA + A_BYTES + (uint32_t)((brow + nj * 16) * 128)
                                   + ((uint32_t)bkoff ^ swz));
        }

        stg  = (stg  == STAGES - 1) ? 0 : stg + 1;
        ldst = (ldst == STAGES - 1) ? 0 : ldst + 1;
    }

    // ---------------- epilogue ---------------------------------------------
    __syncthreads();   // reuse smem for D tile
    float* Ds = (float*)smem;
#pragma unroll
    for (int mi = 0; mi < 4; ++mi) {
#pragma unroll
        for (int cj = 0; cj < 4; ++cj) {
            int r0 = wm0 + mi * 16 + (l >> 2);
            int cb = wn0 + cj * 8 + (l & 3) * 2;
            Ds[r0 * DPITCH + cb]           = acc[mi][cj][0];
            Ds[r0 * DPITCH + cb + 1]       = acc[mi][cj][1];
            Ds[(r0 + 8) * DPITCH + cb]     = acc[mi][cj][2];
            Ds[(r0 + 8) * DPITCH + cb + 1] = acc[mi][cj][3];
        }
    }
    __syncthreads();

    const int ol = tid & 31;          // local output feature 0..31
    const int m0 = tid >> 5;          // 0..7 (16 rows each)
    const int og = by * 32 + ol;      // global output feature
    const float wcf = fg_w_c[og], wci = ig_w_c[og], wco = og_w_cn[og];
    const float bff = fg_b[og], bii = ig_b[og], bnn = in_b[og], boo = og_b[og];

#pragma unroll 4
    for (int r = 0; r < 16; ++r) {
        int m = m0 * 16 + r;
        int b = bx * BM + m;
        float4 z = *(const float4*)&Ds[m * DPITCH + ol * 4];
        float Cv = C[(size_t)b * OUTF + og];
        float zf = z.x + wcf * Cv + bff;
        float zi = z.y + wci * Cv + bii;
        float zn = z.z + bnn;
        float cm = sigf(zf) * Cv + sigf(zi) * tanhf_fast(zn);
        float zo = z.w + wco * cm + boo;
        float h  = sigf(zo) * tanhf_fast(cm);
        out[(size_t)b * OUTF + og] = cm;
        out[(size_t)BATCHN * OUTF + (size_t)b * OUTF + og] = h;
    }
}

// ---------------- launch ----------------------------------------------------
extern "C" void kernel_launch(void* const* d_in, const int* in_sizes, int n_in,
                              void* d_out, int out_size) {
    const float* x      = (const float*)d_in[0];
    const float* C      = (const float*)d_in[1];
    const float* H      = (const float*)d_in[2];
    const float* fg_w_c = (const float*)d_in[3];
    const float* fg_w_h = (const float*)d_in[4];
    const float* fg_w_x = (const float*)d_in[5];
    const float* fg_b   = (const float*)d_in[6];
    const float* ig_w_c = (const float*)d_in[7];
    const float* ig_w_h = (const float*)d_in[8];
    const float* ig_w_x = (const float*)d_in[9];
    const float* ig_b   = (const float*)d_in[10];
    const float* in_w_h = (const float*)d_in[11];
    const float* in_w_x = (const float*)d_in[12];
    const float* in_b   = (const float*)d_in[13];
    const float* og_w_cn= (const float*)d_in[14];
    const float* og_w_h = (const float*)d_in[15];
    const float* og_w_x = (const float*)d_in[16];
    const float* og_b   = (const float*)d_in[17];
    const int*   n      = (const int*)d_in[18];
    float* out = (float*)d_out;

    prep_w_kernel<<<(NROWS * (KSEG / 4) + 255) / 256, 256>>>(
        fg_w_h, fg_w_x, ig_w_h, ig_w_x, in_w_h, in_w_x, og_w_h, og_w_x);
    prep_u_kernel<<<(BATCHN * (KSEG / 4) + 255) / 256, 256>>>(x, H, n);

    static bool attr_done = false;
    if (!attr_done) {
        cudaFuncSetAttribute(lstm_gemm,
                             cudaFuncAttributeMaxDynamicSharedMemorySize, SMEM_TOTAL);
        attr_done = true;
    }
    dim3 grid(BATCHN / BM, NROWS / BN);
    lstm_gemm<<<grid, 256, SMEM_TOTAL>>>(
        C, fg_w_c, fg_b, ig_w_c, ig_b, in_b, og_w_cn, og_b, out);
}